// round 2
// baseline (speedup 1.0000x reference)
#include <cuda_runtime.h>

#define Bb 8
#define Nn 2048
#define CIN 128
#define Ff 64
#define ALPHA 0.01f
#define TI 16
#define TJ 16

// scratch (static __device__ allowed; no dynamic alloc)
__device__ float g_h[Bb * Nn * Ff];     // 4 MB
__device__ float g_s1[Bb * Nn];
__device__ float g_s2[Bb * Nn];
__device__ float g_gm[Bb];

__device__ __forceinline__ unsigned long long ffma2(unsigned long long a,
                                                    unsigned long long b,
                                                    unsigned long long c) {
    unsigned long long d;
    asm("fma.rn.f32x2 %0, %1, %2, %3;" : "=l"(d) : "l"(a), "l"(b), "l"(c));
    return d;
}

// ---------------------------------------------------------------------------
// Kernel 1: h = inp @ W   ([16384,128] @ [128,64])
// block: 256 threads -> 16 rows x 64 cols; W cached in smem.
// ---------------------------------------------------------------------------
__global__ __launch_bounds__(256) void k_h(const float* __restrict__ inp,
                                           const float* __restrict__ W) {
    __shared__ float Ws[CIN * Ff];      // 32 KB
    __shared__ float Is[TI * CIN];      // 8 KB
    const int tid  = threadIdx.x;
    const int row0 = blockIdx.x * TI;   // flat row in [0, 16384)

    for (int i = tid; i < CIN * Ff; i += 256) Ws[i] = W[i];
    for (int i = tid; i < TI * CIN; i += 256) Is[i] = inp[row0 * CIN + i];
    __syncthreads();

    const int col = tid & 63;
    const int r0  = tid >> 6;           // 0..3 -> rows r0, r0+4, r0+8, r0+12
    float acc[4] = {0.f, 0.f, 0.f, 0.f};
    #pragma unroll 4
    for (int c = 0; c < CIN; c++) {
        const float wv = Ws[c * Ff + col];
        #pragma unroll
        for (int k = 0; k < 4; k++)
            acc[k] += Is[(r0 + 4 * k) * CIN + c] * wv;
    }
    #pragma unroll
    for (int k = 0; k < 4; k++)
        g_h[(row0 + r0 + 4 * k) * Ff + col] = acc[k];
}

// ---------------------------------------------------------------------------
// Kernel 2: s1 = h @ a1, s2 = h @ a2   (one warp per row)
// ---------------------------------------------------------------------------
__global__ __launch_bounds__(256) void k_s(const float* __restrict__ a) {
    const int warp = threadIdx.x >> 5;
    const int lane = threadIdx.x & 31;
    const int row  = blockIdx.x * 8 + warp;   // [0, 16384)

    const float2 hv = ((const float2*)(g_h + row * Ff))[lane];
    const float a1l = a[2 * lane],       a1h = a[2 * lane + 1];
    const float a2l = a[Ff + 2 * lane],  a2h = a[Ff + 2 * lane + 1];
    float p1 = hv.x * a1l + hv.y * a1h;
    float p2 = hv.x * a2l + hv.y * a2h;
    #pragma unroll
    for (int o = 16; o; o >>= 1) {
        p1 += __shfl_xor_sync(0xFFFFFFFFu, p1, o);
        p2 += __shfl_xor_sync(0xFFFFFFFFu, p2, o);
    }
    if (lane == 0) {
        g_s1[row] = p1;
        g_s2[row] = p2;
    }
}

// ---------------------------------------------------------------------------
// Kernel 3: g_gm[b] = max_j s2[b,j]  (unmasked global max, valid softmax shift)
// ---------------------------------------------------------------------------
__global__ __launch_bounds__(256) void k_gmax() {
    __shared__ float red[256];
    const int b = blockIdx.x, tid = threadIdx.x;
    float m = -3.0e38f;
    for (int j = tid; j < Nn; j += 256) m = fmaxf(m, g_s2[b * Nn + j]);
    red[tid] = m;
    __syncthreads();
    #pragma unroll
    for (int s = 128; s > 0; s >>= 1) {
        if (tid < s) red[tid] = fmaxf(red[tid], red[tid + s]);
        __syncthreads();
    }
    if (tid == 0) g_gm[b] = red[0];
}

// ---------------------------------------------------------------------------
// Kernel 4: fused mask + exp + softmax-normalized PV accumulation.
// grid: 128 blocks (i-tile of 16 rows, ALL 8 batches). 256 threads.
// warp = batch; lane = (iloc 0..15, fhalf 0..1); acc: 16 x f32x2 regs.
// ---------------------------------------------------------------------------
__global__ __launch_bounds__(256) void k_attn(const float* __restrict__ adj,
                                              float* __restrict__ out) {
    __shared__ float hs[Bb * TJ * Ff];     // 32 KB  [b][jj][f]
    __shared__ float adjs[TJ][TI + 1];     // transposed adj tile
    __shared__ float s2s[Bb * TJ];

    const int tid   = threadIdx.x;
    const int b     = tid >> 5;            // warp id = batch
    const int lane  = tid & 31;
    const int iloc  = lane & 15;
    const int fhalf = lane >> 4;
    const int i0    = blockIdx.x * TI;
    const int iglob = i0 + iloc;

    const int a_ii = tid >> 4;             // adj tile loader mapping
    const int a_jj = tid & 15;

    const float s1v = g_s1[b * Nn + iglob];
    // softmax shift: lrelu(s1 + global max of s2) >= every masked score
    float t = s1v + g_gm[b];
    const float mval = t > 0.f ? t : ALPHA * t;

    unsigned long long acc[16];
    #pragma unroll
    for (int k = 0; k < 16; k++) acc[k] = 0ull;
    float sumw = 0.0f;

    for (int jt = 0; jt < Nn / TJ; jt++) {
        const int j0 = jt * TJ;
        __syncthreads();
        // adj tile (transposed for conflict-free lane reads)
        adjs[a_jj][a_ii] = adj[(i0 + a_ii) * Nn + j0 + a_jj];
        // s2 tile
        if (tid < Bb * TJ) {
            const int bb = tid >> 4, jj = tid & 15;
            s2s[bb * TJ + jj] = g_s2[bb * Nn + j0 + jj];
        }
        // h tile: 8192 floats = 2048 float4, coalesced
        #pragma unroll
        for (int r = 0; r < 8; r++) {
            const int idx = r * 256 + tid;
            const int row = idx >> 4;               // b*16 + jj
            const int f4  = idx & 15;
            const int bb  = row >> 4, jj = row & 15;
            const float4 v =
                *(const float4*)&g_h[(bb * Nn + j0 + jj) * Ff + f4 * 4];
            *(float4*)&hs[row * Ff + f4 * 4] = v;
        }
        __syncthreads();

        #pragma unroll
        for (int jj = 0; jj < TJ; jj++) {
            const float av = adjs[jj][iloc];
            const float sv = s2s[b * TJ + jj];
            const bool mask = (av > 0.0f) || (j0 + jj == iglob);
            float sc = s1v + sv;
            sc = sc > 0.0f ? sc : ALPHA * sc;
            const float w = mask ? __expf(sc - mval) : 0.0f;  // arg <= 0 always
            sumw += w;
            unsigned long long w2;
            asm("mov.b64 %0, {%1, %1};" : "=l"(w2) : "f"(w));
            const unsigned long long* hp = (const unsigned long long*)
                &hs[(b * TJ + jj) * Ff + fhalf * 32];
            #pragma unroll
            for (int k = 0; k < 16; k++) acc[k] = ffma2(w2, hp[k], acc[k]);
        }
    }

    const float inv = 1.0f / sumw;
    float* op = out + ((b * Nn + iglob) * Ff + fhalf * 32);
    #pragma unroll
    for (int k = 0; k < 16; k++) {
        const float lo = __uint_as_float((unsigned)(acc[k] & 0xFFFFFFFFull));
        const float hi = __uint_as_float((unsigned)(acc[k] >> 32));
        float2 v = make_float2(lo * inv, hi * inv);
        *(float2*)&op[2 * k] = v;
    }
}

// ---------------------------------------------------------------------------
extern "C" void kernel_launch(void* const* d_in, const int* in_sizes, int n_in,
                              void* d_out, int out_size) {
    const float* inp = (const float*)d_in[0];   // [8,2048,128]
    const float* adj = (const float*)d_in[1];   // [2048,2048]
    const float* W   = (const float*)d_in[2];   // [128,64]
    const float* a   = (const float*)d_in[3];   // [128,1]
    float* out = (float*)d_out;                 // [8,2048,64]

    k_h   <<<(Bb * Nn) / TI, 256>>>(inp, W);
    k_s   <<<(Bb * Nn) / 8, 256>>>(a);
    k_gmax<<<Bb, 256>>>();
    k_attn<<<Nn / TI, 256>>>(adj, out);
}

// round 3
// speedup vs baseline: 2.0143x; 2.0143x over previous
#include <cuda_runtime.h>

#define Bb 8
#define Nn 2048
#define CIN 128
#define Ff 64
#define ALPHA 0.01f
#define TI 16
#define TJ 16
#define JS 8                         // j-dimension splits
#define JT_PER_SPLIT (Nn / TJ / JS)  // 16

// scratch (static __device__ allowed; no dynamic alloc)
__device__ float g_h[Bb * Nn * Ff];             // 4 MB
__device__ float g_s1[Bb * Nn];
__device__ float g_s2[Bb * Nn];
__device__ float g_gm[Bb];
__device__ float g_part[JS * Bb * Nn * Ff];     // 33.5 MB partial weighted sums
__device__ float g_psum[JS * Bb * Nn];          // partial softmax denominators

__device__ __forceinline__ unsigned long long ffma2(unsigned long long a,
                                                    unsigned long long b,
                                                    unsigned long long c) {
    unsigned long long d;
    asm("fma.rn.f32x2 %0, %1, %2, %3;" : "=l"(d) : "l"(a), "l"(b), "l"(c));
    return d;
}

// ---------------------------------------------------------------------------
// Kernel 1: h = inp @ W   ([16384,128] @ [128,64])
// ---------------------------------------------------------------------------
__global__ __launch_bounds__(256) void k_h(const float* __restrict__ inp,
                                           const float* __restrict__ W) {
    __shared__ float Ws[CIN * Ff];      // 32 KB
    __shared__ float Is[TI * CIN];      // 8 KB
    const int tid  = threadIdx.x;
    const int row0 = blockIdx.x * TI;

    for (int i = tid; i < CIN * Ff; i += 256) Ws[i] = W[i];
    for (int i = tid; i < TI * CIN; i += 256) Is[i] = inp[row0 * CIN + i];
    __syncthreads();

    const int col = tid & 63;
    const int r0  = tid >> 6;
    float acc[4] = {0.f, 0.f, 0.f, 0.f};
    #pragma unroll 4
    for (int c = 0; c < CIN; c++) {
        const float wv = Ws[c * Ff + col];
        #pragma unroll
        for (int k = 0; k < 4; k++)
            acc[k] += Is[(r0 + 4 * k) * CIN + c] * wv;
    }
    #pragma unroll
    for (int k = 0; k < 4; k++)
        g_h[(row0 + r0 + 4 * k) * Ff + col] = acc[k];
}

// ---------------------------------------------------------------------------
// Kernel 2: s1 = h @ a1, s2 = h @ a2   (one warp per row)
// ---------------------------------------------------------------------------
__global__ __launch_bounds__(256) void k_s(const float* __restrict__ a) {
    const int warp = threadIdx.x >> 5;
    const int lane = threadIdx.x & 31;
    const int row  = blockIdx.x * 8 + warp;

    const float2 hv = ((const float2*)(g_h + row * Ff))[lane];
    const float a1l = a[2 * lane],       a1h = a[2 * lane + 1];
    const float a2l = a[Ff + 2 * lane],  a2h = a[Ff + 2 * lane + 1];
    float p1 = hv.x * a1l + hv.y * a1h;
    float p2 = hv.x * a2l + hv.y * a2h;
    #pragma unroll
    for (int o = 16; o; o >>= 1) {
        p1 += __shfl_xor_sync(0xFFFFFFFFu, p1, o);
        p2 += __shfl_xor_sync(0xFFFFFFFFu, p2, o);
    }
    if (lane == 0) {
        g_s1[row] = p1;
        g_s2[row] = p2;
    }
}

// ---------------------------------------------------------------------------
// Kernel 3: g_gm[b] = max_j s2[b,j]  (unmasked global max = valid softmax shift)
// ---------------------------------------------------------------------------
__global__ __launch_bounds__(256) void k_gmax() {
    __shared__ float red[256];
    const int b = blockIdx.x, tid = threadIdx.x;
    float m = -3.0e38f;
    for (int j = tid; j < Nn; j += 256) m = fmaxf(m, g_s2[b * Nn + j]);
    red[tid] = m;
    __syncthreads();
    #pragma unroll
    for (int s = 128; s > 0; s >>= 1) {
        if (tid < s) red[tid] = fmaxf(red[tid], red[tid + s]);
        __syncthreads();
    }
    if (tid == 0) g_gm[b] = red[0];
}

// ---------------------------------------------------------------------------
// Kernel 4: fused mask + exp + partial PV accumulation over a j-range.
// grid: (128 i-tiles, JS splits). 256 threads. warp = batch;
// lane = (iloc 0..15, fhalf 0..1); acc: 16 x f32x2 regs; LDS.128 h loads.
// ---------------------------------------------------------------------------
__global__ __launch_bounds__(256, 3) void k_attn(const float* __restrict__ adj) {
    __shared__ float hs[Bb * TJ * Ff];     // 32 KB  [b][jj][f]
    __shared__ float adjs[TJ][TI + 1];     // transposed adj tile
    __shared__ float s2s[Bb * TJ];

    const int tid   = threadIdx.x;
    const int b     = tid >> 5;            // warp id = batch
    const int lane  = tid & 31;
    const int iloc  = lane & 15;
    const int fhalf = lane >> 4;
    const int i0    = blockIdx.x * TI;
    const int split = blockIdx.y;
    const int iglob = i0 + iloc;

    const int a_ii = tid >> 4;
    const int a_jj = tid & 15;

    const float s1v = g_s1[b * Nn + iglob];
    float t = s1v + g_gm[b];
    const float mval = t > 0.f ? t : ALPHA * t;

    unsigned long long acc[16];
    #pragma unroll
    for (int k = 0; k < 16; k++) acc[k] = 0ull;
    float sumw = 0.0f;

    const int jt0 = split * JT_PER_SPLIT;
    for (int jt = jt0; jt < jt0 + JT_PER_SPLIT; jt++) {
        const int j0 = jt * TJ;
        __syncthreads();
        adjs[a_jj][a_ii] = adj[(i0 + a_ii) * Nn + j0 + a_jj];
        if (tid < Bb * TJ) {
            const int bb = tid >> 4, jj = tid & 15;
            s2s[bb * TJ + jj] = g_s2[bb * Nn + j0 + jj];
        }
        #pragma unroll
        for (int r = 0; r < 8; r++) {
            const int idx = r * 256 + tid;
            const int row = idx >> 4;
            const int f4  = idx & 15;
            const int bb  = row >> 4, jj = row & 15;
            const float4 v =
                *(const float4*)&g_h[(bb * Nn + j0 + jj) * Ff + f4 * 4];
            *(float4*)&hs[row * Ff + f4 * 4] = v;
        }
        __syncthreads();

        #pragma unroll
        for (int jj = 0; jj < TJ; jj++) {
            const float av = adjs[jj][iloc];
            const float sv = s2s[b * TJ + jj];
            const bool mask = (av > 0.0f) || (j0 + jj == iglob);
            float sc = s1v + sv;
            sc = sc > 0.0f ? sc : ALPHA * sc;
            const float w = mask ? __expf(sc - mval) : 0.0f;  // arg <= 0 always
            sumw += w;
            unsigned long long w2;
            asm("mov.b64 %0, {%1, %1};" : "=l"(w2) : "f"(w));
            const ulonglong2* hp = (const ulonglong2*)
                &hs[(b * TJ + jj) * Ff + fhalf * 32];
            #pragma unroll
            for (int k = 0; k < 8; k++) {
                const ulonglong2 v = hp[k];
                acc[2 * k]     = ffma2(w2, v.x, acc[2 * k]);
                acc[2 * k + 1] = ffma2(w2, v.y, acc[2 * k + 1]);
            }
        }
    }

    // write partials
    unsigned long long* pp = (unsigned long long*)
        &g_part[((split * Bb + b) * Nn + iglob) * Ff + fhalf * 32];
    #pragma unroll
    for (int k = 0; k < 16; k++) pp[k] = acc[k];
    if (fhalf == 0)
        g_psum[(split * Bb + b) * Nn + iglob] = sumw;
}

// ---------------------------------------------------------------------------
// Kernel 5: reduce splits + normalize. block = 256 threads = 4 rows x 64 f.
// ---------------------------------------------------------------------------
__global__ __launch_bounds__(256) void k_norm(float* __restrict__ out) {
    const int tid = threadIdx.x;
    const int row = blockIdx.x * 4 + (tid >> 6);   // (b*Nn + i), [0, 16384)
    const int f   = tid & 63;

    float den = 0.0f;
    #pragma unroll
    for (int s = 0; s < JS; s++) den += g_psum[s * Bb * Nn + row];

    float num = 0.0f;
    #pragma unroll
    for (int s = 0; s < JS; s++)
        num += g_part[(s * Bb * Nn + row) * Ff + f];

    out[row * Ff + f] = num / den;
}

// ---------------------------------------------------------------------------
extern "C" void kernel_launch(void* const* d_in, const int* in_sizes, int n_in,
                              void* d_out, int out_size) {
    const float* inp = (const float*)d_in[0];   // [8,2048,128]
    const float* adj = (const float*)d_in[1];   // [2048,2048]
    const float* W   = (const float*)d_in[2];   // [128,64]
    const float* a   = (const float*)d_in[3];   // [128,1]
    float* out = (float*)d_out;                 // [8,2048,64]

    k_h   <<<(Bb * Nn) / TI, 256>>>(inp, W);
    k_s   <<<(Bb * Nn) / 8, 256>>>(a);
    k_gmax<<<Bb, 256>>>();
    dim3 grid_attn(Nn / TI, JS);
    k_attn<<<grid_attn, 256>>>(adj);
    k_norm<<<(Bb * Nn) / 4, 256>>>(out);
}

// round 4
// speedup vs baseline: 2.7680x; 1.3741x over previous
#include <cuda_runtime.h>

#define Bb 8
#define Nn 2048
#define CIN 128
#define Ff 64
#define ALPHA 0.01f
#define TI 16
#define TJ 16
#define JS 8                         // j-dimension splits
#define JT_PER_SPLIT (Nn / TJ / JS)  // 16

__device__ float g_h[Bb * Nn * Ff];             // 4 MB
__device__ float g_s1[Bb * Nn];
__device__ float g_s2[Bb * Nn];
__device__ float g_gm[Bb];
__device__ float g_part[JS * Bb * Nn * Ff];     // 33.5 MB partial weighted sums
__device__ float g_psum[JS * Bb * Nn];          // partial softmax denominators

__device__ __forceinline__ unsigned long long ffma2(unsigned long long a,
                                                    unsigned long long b,
                                                    unsigned long long c) {
    unsigned long long d;
    asm("fma.rn.f32x2 %0, %1, %2, %3;" : "=l"(d) : "l"(a), "l"(b), "l"(c));
    return d;
}

// ---------------------------------------------------------------------------
// Kernel 1: h = inp @ W   ([16384,128] @ [128,64])
// ---------------------------------------------------------------------------
__global__ __launch_bounds__(256) void k_h(const float* __restrict__ inp,
                                           const float* __restrict__ W) {
    __shared__ float Ws[CIN * Ff];
    __shared__ float Is[TI * CIN];
    const int tid  = threadIdx.x;
    const int row0 = blockIdx.x * TI;

    for (int i = tid; i < CIN * Ff; i += 256) Ws[i] = W[i];
    for (int i = tid; i < TI * CIN; i += 256) Is[i] = inp[row0 * CIN + i];
    __syncthreads();

    const int col = tid & 63;
    const int r0  = tid >> 6;
    float acc[4] = {0.f, 0.f, 0.f, 0.f};
    #pragma unroll 4
    for (int c = 0; c < CIN; c++) {
        const float wv = Ws[c * Ff + col];
        #pragma unroll
        for (int k = 0; k < 4; k++)
            acc[k] += Is[(r0 + 4 * k) * CIN + c] * wv;
    }
    #pragma unroll
    for (int k = 0; k < 4; k++)
        g_h[(row0 + r0 + 4 * k) * Ff + col] = acc[k];
}

// ---------------------------------------------------------------------------
// Kernel 2: s1 = h @ a1, s2 = h @ a2   (one warp per row)
// ---------------------------------------------------------------------------
__global__ __launch_bounds__(256) void k_s(const float* __restrict__ a) {
    const int warp = threadIdx.x >> 5;
    const int lane = threadIdx.x & 31;
    const int row  = blockIdx.x * 8 + warp;

    const float2 hv = ((const float2*)(g_h + row * Ff))[lane];
    const float a1l = a[2 * lane],       a1h = a[2 * lane + 1];
    const float a2l = a[Ff + 2 * lane],  a2h = a[Ff + 2 * lane + 1];
    float p1 = hv.x * a1l + hv.y * a1h;
    float p2 = hv.x * a2l + hv.y * a2h;
    #pragma unroll
    for (int o = 16; o; o >>= 1) {
        p1 += __shfl_xor_sync(0xFFFFFFFFu, p1, o);
        p2 += __shfl_xor_sync(0xFFFFFFFFu, p2, o);
    }
    if (lane == 0) {
        g_s1[row] = p1;
        g_s2[row] = p2;
    }
}

// ---------------------------------------------------------------------------
// Kernel 3: g_gm[b] = max_j s2[b,j]  (unmasked global max = valid softmax shift)
// ---------------------------------------------------------------------------
__global__ __launch_bounds__(256) void k_gmax() {
    __shared__ float red[256];
    const int b = blockIdx.x, tid = threadIdx.x;
    float m = -3.0e38f;
    for (int j = tid; j < Nn; j += 256) m = fmaxf(m, g_s2[b * Nn + j]);
    red[tid] = m;
    __syncthreads();
    #pragma unroll
    for (int s = 128; s > 0; s >>= 1) {
        if (tid < s) red[tid] = fmaxf(red[tid], red[tid + s]);
        __syncthreads();
    }
    if (tid == 0) g_gm[b] = red[0];
}

// ---------------------------------------------------------------------------
// Kernel 4: fused mask + exp + partial PV accumulation over a j-range.
// warp = batch. Lane owns f-columns {lane, lane+32} for ALL 16 i rows.
// Phase 1 (warp-local): compute w[i][jj] tile -> wsm (i-pairs contiguous).
// Phase 2: outer product; w read as broadcast LDS.128 (pre-packed f32x2),
//          h read as 2 distinct LDS.32 -> minimal crossbar traffic.
// ---------------------------------------------------------------------------
__global__ __launch_bounds__(256, 3) void k_attn(const float* __restrict__ adj) {
    __shared__ __align__(16) float hs[Bb * TJ * Ff];   // 32 KB  [b][jj][f]
    __shared__ float adjs[TJ][TI + 1];                 // transposed adj tile
    __shared__ float s2s[Bb * TJ];
    __shared__ __align__(16) float wsm[Bb][TJ][TI];    // 8 KB warp-private w

    const int tid   = threadIdx.x;
    const int b     = tid >> 5;            // warp id = batch
    const int lane  = tid & 31;
    const int il    = lane & 15;           // phase-1 i row
    const int jjo   = lane >> 4;           // phase-1 jj parity
    const int i0    = blockIdx.x * TI;
    const int split = blockIdx.y;
    const int ig1   = i0 + il;

    const int a_ii = tid >> 4;
    const int a_jj = tid & 15;

    const float s1v = g_s1[b * Nn + ig1];
    float t = s1v + g_gm[b];
    const float mval = t > 0.f ? t : ALPHA * t;   // >= every masked score

    unsigned long long acc[2][8];          // [fgroup][ipair] f32x2 over i
    #pragma unroll
    for (int g = 0; g < 2; g++)
        #pragma unroll
        for (int p = 0; p < 8; p++) acc[g][p] = 0ull;
    float sumw = 0.0f;

    const int jt0 = split * JT_PER_SPLIT;
    for (int jt = jt0; jt < jt0 + JT_PER_SPLIT; jt++) {
        const int j0 = jt * TJ;
        __syncthreads();
        adjs[a_jj][a_ii] = adj[(i0 + a_ii) * Nn + j0 + a_jj];
        if (tid < Bb * TJ)
            s2s[tid] = g_s2[(tid >> 4) * Nn + j0 + (tid & 15)];
        #pragma unroll
        for (int r = 0; r < 8; r++) {
            const int idx = r * 256 + tid;
            const int row = idx >> 4;              // b*16 + jj
            const int f4  = idx & 15;
            const int bb  = row >> 4, jj = row & 15;
            const float4 v =
                *(const float4*)&g_h[(bb * Nn + j0 + jj) * Ff + f4 * 4];
            *(float4*)&hs[row * Ff + f4 * 4] = v;
        }
        __syncthreads();

        // ---- phase 1: weights for this tile (warp-private) ----
        #pragma unroll
        for (int u = 0; u < 8; u++) {
            const int jj = 2 * u + jjo;
            const float av = adjs[jj][il];
            const float sv = s2s[b * TJ + jj];
            const bool mask = (av > 0.0f) || (j0 + jj == ig1);
            float sc = s1v + sv;
            sc = sc > 0.0f ? sc : ALPHA * sc;
            const float w = mask ? __expf(sc - mval) : 0.0f;  // arg <= 0
            sumw += w;
            wsm[b][jj][il] = w;
        }
        __syncwarp();

        // ---- phase 2: rank-16 outer-product update ----
        #pragma unroll
        for (int jj = 0; jj < TJ; jj++) {
            const float h0 = hs[(b * TJ + jj) * Ff + lane];
            const float h1 = hs[(b * TJ + jj) * Ff + lane + 32];
            unsigned long long hh0, hh1;
            asm("mov.b64 %0, {%1, %1};" : "=l"(hh0) : "f"(h0));
            asm("mov.b64 %0, {%1, %1};" : "=l"(hh1) : "f"(h1));
            const ulonglong2* wp = (const ulonglong2*)&wsm[b][jj][0];
            #pragma unroll
            for (int q = 0; q < 4; q++) {
                const ulonglong2 wv = wp[q];      // broadcast LDS.128
                acc[0][2 * q]     = ffma2(wv.x, hh0, acc[0][2 * q]);
                acc[1][2 * q]     = ffma2(wv.x, hh1, acc[1][2 * q]);
                acc[0][2 * q + 1] = ffma2(wv.y, hh0, acc[0][2 * q + 1]);
                acc[1][2 * q + 1] = ffma2(wv.y, hh1, acc[1][2 * q + 1]);
            }
        }
        __syncwarp();
    }

    // ---- epilogue: write partials (coalesced 128B per (i, fgroup)) ----
    float* base = &g_part[((split * Bb + b) * Nn + i0) * Ff];
    #pragma unroll
    for (int p = 0; p < 8; p++) {
        #pragma unroll
        for (int g = 0; g < 2; g++) {
            const unsigned long long v = acc[g][p];
            const float lo = __uint_as_float((unsigned)(v & 0xFFFFFFFFull));
            const float hi = __uint_as_float((unsigned)(v >> 32));
            base[(2 * p)     * Ff + lane + 32 * g] = lo;
            base[(2 * p + 1) * Ff + lane + 32 * g] = hi;
        }
    }
    sumw += __shfl_xor_sync(0xFFFFFFFFu, sumw, 16);
    if (lane < 16)
        g_psum[(split * Bb + b) * Nn + i0 + lane] = sumw;
}

// ---------------------------------------------------------------------------
// Kernel 5: reduce splits + normalize. block = 256 threads = 4 rows x 64 f.
// ---------------------------------------------------------------------------
__global__ __launch_bounds__(256) void k_norm(float* __restrict__ out) {
    const int tid = threadIdx.x;
    const int row = blockIdx.x * 4 + (tid >> 6);   // (b*Nn + i)
    const int f   = tid & 63;

    float den = 0.0f;
    #pragma unroll
    for (int s = 0; s < JS; s++) den += g_psum[s * Bb * Nn + row];

    float num = 0.0f;
    #pragma unroll
    for (int s = 0; s < JS; s++)
        num += g_part[(s * Bb * Nn + row) * Ff + f];

    out[row * Ff + f] = num / den;
}

// ---------------------------------------------------------------------------
extern "C" void kernel_launch(void* const* d_in, const int* in_sizes, int n_in,
                              void* d_out, int out_size) {
    const float* inp = (const float*)d_in[0];   // [8,2048,128]
    const float* adj = (const float*)d_in[1];   // [2048,2048]
    const float* W   = (const float*)d_in[2];   // [128,64]
    const float* a   = (const float*)d_in[3];   // [128,1]
    float* out = (float*)d_out;                 // [8,2048,64]

    k_h   <<<(Bb * Nn) / TI, 256>>>(inp, W);
    k_s   <<<(Bb * Nn) / 8, 256>>>(a);
    k_gmax<<<Bb, 256>>>();
    dim3 grid_attn(Nn / TI, JS);
    k_attn<<<grid_attn, 256>>>(adj);
    k_norm<<<(Bb * Nn) / 4, 256>>>(out);
}